// round 17
// baseline (speedup 1.0000x reference)
#include <cuda_runtime.h>
#include <cuda_fp16.h>
#include <cstdint>
#include <cstddef>

#define NPTS   4096
#define MANCH  128
#define GC0    64
#define GC1    128
#define KNN    32
#define RR2    0.0225f
#define GTOT   64
#define FPS_THREADS 1024
#define FS     66    // B-fragment stride in words (64 + 2 pad)

// Layer-1 weights (1KB — const-cache resident, warp-uniform reads)
__constant__ float4 cWd[GC0];
// Layer-2 weights as fp16x2 in m16n8k16 A-fragment layout (16KB, L1-resident)
__device__ uint32_t gWmF16[8 * 4 * 128];

// Exact (non-FMA-contracted) squared distance: discrete decisions
// (radius threshold) match the JAX reference bit-for-bit.
__device__ __forceinline__ float dist2_precise(float ax, float ay, float az,
                                               float bx, float by, float bz) {
    float dx = __fsub_rn(ax, bx);
    float dy = __fsub_rn(ay, by);
    float dz = __fsub_rn(az, bz);
    return __fadd_rn(__fadd_rn(__fmul_rn(dx, dx), __fmul_rn(dy, dy)),
                     __fmul_rn(dz, dz));
}

// ---- packed f32x2 helpers (per-lane rounding identical to scalar ops) ----
typedef unsigned long long u64t;
__device__ __forceinline__ u64t pk2f(float lo, float hi) {
    u64t r; asm("mov.b64 %0, {%1, %2};" : "=l"(r) : "f"(lo), "f"(hi)); return r;
}
__device__ __forceinline__ void upk2f(float& lo, float& hi, u64t v) {
    asm("mov.b64 {%0, %1}, %2;" : "=f"(lo), "=f"(hi) : "l"(v));
}
__device__ __forceinline__ u64t sub2(u64t a, u64t b) {
    u64t d; asm("sub.rn.f32x2 %0, %1, %2;" : "=l"(d) : "l"(a), "l"(b)); return d;
}
__device__ __forceinline__ u64t mul2(u64t a, u64t b) {
    u64t d; asm("mul.rn.f32x2 %0, %1, %2;" : "=l"(d) : "l"(a), "l"(b)); return d;
}
__device__ __forceinline__ u64t add2(u64t a, u64t b) {
    u64t d; asm("add.rn.f32x2 %0, %1, %2;" : "=l"(d) : "l"(a), "l"(b)); return d;
}

__device__ __forceinline__ unsigned redux_max_u32(unsigned v) {
    unsigned r;
    asm("redux.sync.max.u32 %0, %1, 0xffffffff;" : "=r"(r) : "r"(v));
    return r;
}
__device__ __forceinline__ unsigned redux_min_u32(unsigned v) {
    unsigned r;
    asm("redux.sync.min.u32 %0, %1, 0xffffffff;" : "=r"(r) : "r"(v));
    return r;
}

// pack two fp32 -> fp16x2 (lo in low half)
__device__ __forceinline__ uint32_t pkh2(float lo, float hi) {
    uint32_t r;
    asm("cvt.rn.f16x2.f32 %0, %1, %2;" : "=r"(r) : "f"(hi), "f"(lo));
    return r;
}

__device__ __forceinline__ void mma_f16(float& d0, float& d1, float& d2, float& d3,
                                        uint32_t a0, uint32_t a1, uint32_t a2, uint32_t a3,
                                        uint32_t b0, uint32_t b1) {
    asm volatile(
        "mma.sync.aligned.m16n8k16.row.col.f32.f16.f16.f32 "
        "{%0,%1,%2,%3}, {%4,%5,%6,%7}, {%8,%9}, {%0,%1,%2,%3};"
        : "+f"(d0), "+f"(d1), "+f"(d2), "+f"(d3)
        : "r"(a0), "r"(a1), "r"(a2), "r"(a3), "r"(b0), "r"(b1));
}

// ---------------------------------------------------------------------------
// Kernel A: FPS (blocks 0..63) + Wm fragment prep (blocks 64..67).
// Packed f32x2 distance arithmetic (bit-exact per lane); deferred argmax
// with exact first-occurrence tie-break (matches jnp.argmax).
// ---------------------------------------------------------------------------
__global__ void __launch_bounds__(FPS_THREADS) fps_kernel(
    const float* __restrict__ xyzs, const float* __restrict__ Wm,
    float* __restrict__ out) {
    if (blockIdx.x >= GTOT) {
        int idx = (blockIdx.x - GTOT) * FPS_THREADS + threadIdx.x;  // 0..4095
        int r = idx & 3;
        int l = (idx >> 2) & 31;
        int fid = idx >> 7;
        int kt = fid & 3, mt = fid >> 2;
        int gid = l >> 2, tig = l & 3;
        int row = mt * 16 + gid + (r & 1) * 8;
        int ch  = kt * 16 + tig * 2 + (r >> 1) * 8;
        gWmF16[idx] = pkh2(Wm[row * GC0 + ch], Wm[row * GC0 + ch + 1]);
        return;
    }

    extern __shared__ float sm[];
    float* sx = sm;
    float* sy = sm + NPTS;
    float* sz = sm + 2 * NPTS;
    __shared__ float redV[2][32];
    __shared__ int   redI[2][32];

    int g = blockIdx.x;
    int b = g >> 4, f = g & 15;
    const float* frame = xyzs + ((size_t)(b * 32 + 2 * f)) * NPTS * 3;
    int tid = threadIdx.x, lane = tid & 31, wid = tid >> 5;

    for (int i = tid; i < NPTS; i += FPS_THREADS) {
        sx[i] = frame[3 * i + 0];
        sy[i] = frame[3 * i + 1];
        sz[i] = frame[3 * i + 2];
    }
    __syncthreads();

    u64t X2[2], Y2[2], Z2[2];
    float dist[4];
#pragma unroll
    for (int p = 0; p < 2; p++) {
        int i0 = tid + 2 * p * FPS_THREADS;
        X2[p] = pk2f(sx[i0], sx[i0 + FPS_THREADS]);
        Y2[p] = pk2f(sy[i0], sy[i0 + FPS_THREADS]);
        Z2[p] = pk2f(sz[i0], sz[i0 + FPS_THREADS]);
    }
#pragma unroll
    for (int s = 0; s < 4; s++) dist[s] = 1e10f;

    if (tid == 0) {
        float* ap = out + (size_t)g * MANCH * 3;
        ap[0] = sx[0]; ap[1] = sy[0]; ap[2] = sz[0];
    }
    float px = sx[0], py = sy[0], pz = sz[0];

    for (int step = 1; step < MANCH; step++) {
        int par = step & 1;
        u64t pxx = pk2f(px, px), pyy = pk2f(py, py), pzz = pk2f(pz, pz);
        float nd[4];
#pragma unroll
        for (int p = 0; p < 2; p++) {
            u64t dx = sub2(X2[p], pxx);
            u64t dy = sub2(Y2[p], pyy);
            u64t dz = sub2(Z2[p], pzz);
            u64t d2 = add2(add2(mul2(dx, dx), mul2(dy, dy)), mul2(dz, dz));
            upk2f(nd[2 * p], nd[2 * p + 1], d2);
        }
        float bv = -1.0f;
#pragma unroll
        for (int s = 0; s < 4; s++) {
            dist[s] = fminf(dist[s], nd[s]);
            bv = fmaxf(bv, dist[s]);
        }
        unsigned wm = redux_max_u32(__float_as_uint(bv));
        unsigned ci = 0x7FFFFFFFu;
        if (__float_as_uint(dist[3]) == wm) ci = (unsigned)(tid + 3 * FPS_THREADS);
        if (__float_as_uint(dist[2]) == wm) ci = (unsigned)(tid + 2 * FPS_THREADS);
        if (__float_as_uint(dist[1]) == wm) ci = (unsigned)(tid + FPS_THREADS);
        if (__float_as_uint(dist[0]) == wm) ci = (unsigned)tid;
        unsigned wi = redux_min_u32(ci);
        if (lane == 0) { redV[par][wid] = __uint_as_float(wm); redI[par][wid] = (int)wi; }
        __syncthreads();
        float    v  = redV[par][lane];
        unsigned ix = (unsigned)redI[par][lane];
        unsigned gmx = redux_max_u32(__float_as_uint(v));
        unsigned ci2 = (__float_as_uint(v) == gmx) ? ix : 0x7FFFFFFFu;
        int gi = (int)redux_min_u32(ci2);
        px = sx[gi]; py = sy[gi]; pz = sz[gi];
        if (tid == 0) {
            float* ap = out + ((size_t)g * MANCH + step) * 3;
            ap[0] = px; ap[1] = py; ap[2] = pz;
        }
    }
}

// ---------------------------------------------------------------------------
// Kernel B (FUSED): ball query (LDG scan of AoS frame) + layer1 + fp16
// m16n8k16 MMA + max-over-k + sum-over-dt. Grid (16,64), block 256 = 8
// warps, warp = one anchor, 3 dts sequential. No point staging in smem —
// frames are L1-resident; smem holds only B fragments + ib.
// ---------------------------------------------------------------------------
__global__ void __launch_bounds__(256, 3) conv_kernel(
    const float* __restrict__ xyzs,
    float* __restrict__ out) {
    extern __shared__ uint32_t smB[];            // 8 warps * 16 frags * FS
    int* sidx = (int*)(smB + 8 * 16 * FS);       // 8 warps * 32

    int tile = blockIdx.x, g = blockIdx.y;
    int b = g >> 4, f = g & 15;
    int tid = threadIdx.x, warp = tid >> 5, lane = tid & 31;
    int gid = lane >> 2, tig = lane & 3;
    uint32_t* wB = smB + warp * 16 * FS;
    int* ib = sidx + warp * KNN;
    int m = tile * 8 + warp;

    int ntp = lane >> 3, g8 = lane & 7;
    unsigned lt = (1u << lane) - 1u;

    const float* ap = out + ((size_t)g * MANCH + m) * 3;
    float ax = ap[0], ay = ap[1], az = ap[2];

    float accM[16];
#pragma unroll
    for (int i = 0; i < 16; i++) accM[i] = 0.0f;

    for (int dtI = 0; dtI < 3; dtI++) {
        int t = 2 * f + dtI - 1;
        t = t < 0 ? 0 : (t > 31 ? 31 : t);
        const float* frame = xyzs + ((size_t)(b * 32 + t)) * NPTS * 3;
        float dtf = (float)(dtI - 1);

        // ---- ball query: LDG scan, 4 points/lane/iter, exact first-KNN order
        int count = 0;
        for (int base = 0; base < NPTS && count < KNN; base += 128) {
            int i0 = base + lane * 4;
            const float4* fp = (const float4*)(frame + 3 * i0);
            float4 qa = fp[0], qb = fp[1], qc = fp[2];
            // p0=(qa.x,qa.y,qa.z) p1=(qa.w,qb.x,qb.y) p2=(qb.z,qb.w,qc.x) p3=(qc.y,qc.z,qc.w)
            bool w0 = dist2_precise(ax, ay, az, qa.x, qa.y, qa.z) < RR2;
            bool w1 = dist2_precise(ax, ay, az, qa.w, qb.x, qb.y) < RR2;
            bool w2 = dist2_precise(ax, ay, az, qb.z, qb.w, qc.x) < RR2;
            bool w3 = dist2_precise(ax, ay, az, qc.y, qc.z, qc.w) < RR2;
            unsigned m0 = __ballot_sync(0xffffffffu, w0);
            unsigned m1 = __ballot_sync(0xffffffffu, w1);
            unsigned m2 = __ballot_sync(0xffffffffu, w2);
            unsigned m3 = __ballot_sync(0xffffffffu, w3);
            int r = count + __popc(m0 & lt) + __popc(m1 & lt)
                          + __popc(m2 & lt) + __popc(m3 & lt);
            if (w0) { if (r < KNN) ib[r] = i0;     r++; }
            if (w1) { if (r < KNN) ib[r] = i0 + 1; r++; }
            if (w2) { if (r < KNN) ib[r] = i0 + 2; r++; }
            if (w3) { if (r < KNN) ib[r] = i0 + 3; r++; }
            count += __popc(m0) + __popc(m1) + __popc(m2) + __popc(m3);
        }
        __syncwarp();
        int myIdx = 0;  // no valid neighbor -> index 0 (reference semantics)
        if (count > 0) myIdx = ib[lane < count ? lane : 0];

        float dx = frame[3 * myIdx + 0] - ax;
        float dy = frame[3 * myIdx + 1] - ay;
        float dz = frame[3 * myIdx + 2] - az;

        // ---- layer 1 (fp32) -> fp16 B fragments (fragment-major, FS pad)
#pragma unroll
        for (int kt = 0; kt < 4; kt++) {
            float hv[16];
#pragma unroll
            for (int c = 0; c < 16; c++) {
                float4 w = cWd[kt * 16 + c];
                float v = fmaf(w.x, dx, fmaf(w.y, dy, fmaf(w.z, dz, w.w * dtf)));
                hv[c] = fmaxf(v, 0.0f);
            }
#pragma unroll
            for (int tg = 0; tg < 4; tg++) {
                uint2 v;
                v.x = pkh2(hv[2 * tg],     hv[2 * tg + 1]);
                v.y = pkh2(hv[2 * tg + 8], hv[2 * tg + 9]);
                *(uint2*)(wB + (kt * 4 + ntp) * FS + (g8 * 4 + tg) * 2) = v;
            }
        }
        __syncwarp();

        // ---- layer 2: D[128 o x 32 k] via 128 mma.m16n8k16 (fp16)
#pragma unroll 1
        for (int mt = 0; mt < 8; mt++) {
            float d[4][4];
#pragma unroll
            for (int nt = 0; nt < 4; nt++)
#pragma unroll
                for (int r = 0; r < 4; r++) d[nt][r] = 0.0f;

#pragma unroll
            for (int kt = 0; kt < 4; kt++) {
                uint4 afr = *(const uint4*)&gWmF16[((mt * 4 + kt) * 32 + lane) * 4];
#pragma unroll
                for (int nt = 0; nt < 4; nt++) {
                    uint2 bf = *(const uint2*)(wB + (kt * 4 + nt) * FS + lane * 2);
                    mma_f16(d[nt][0], d[nt][1], d[nt][2], d[nt][3],
                            afr.x, afr.y, afr.z, afr.w, bf.x, bf.y);
                }
            }
            // epilogue: max over neighbors (cols), relu, accumulate over dt
            float mlo = fmaxf(d[0][0], d[0][1]);
            float mhi = fmaxf(d[0][2], d[0][3]);
#pragma unroll
            for (int nt = 1; nt < 4; nt++) {
                mlo = fmaxf(mlo, fmaxf(d[nt][0], d[nt][1]));
                mhi = fmaxf(mhi, fmaxf(d[nt][2], d[nt][3]));
            }
            mlo = fmaxf(mlo, __shfl_xor_sync(0xffffffffu, mlo, 1));
            mlo = fmaxf(mlo, __shfl_xor_sync(0xffffffffu, mlo, 2));
            mhi = fmaxf(mhi, __shfl_xor_sync(0xffffffffu, mhi, 1));
            mhi = fmaxf(mhi, __shfl_xor_sync(0xffffffffu, mhi, 2));
            accM[2 * mt]     += fmaxf(mlo, 0.0f);
            accM[2 * mt + 1] += fmaxf(mhi, 0.0f);
        }
        __syncwarp();  // B reads done before next dt's producer overwrites
    }

    // ---- write new_features: out[b,f,o,m] after the new_xyzs block
    float* feat = out + (size_t)GTOT * MANCH * 3;
    if (tig == 0) {
#pragma unroll
        for (int mt = 0; mt < 8; mt++) {
            int o_lo = mt * 16 + gid;
            feat[((size_t)g * GC1 + o_lo) * MANCH + m]     = accM[2 * mt];
            feat[((size_t)g * GC1 + o_lo + 8) * MANCH + m] = accM[2 * mt + 1];
        }
    }
}

extern "C" void kernel_launch(void* const* d_in, const int* in_sizes, int n_in,
                              void* d_out, int out_size) {
    const float* xyzs = (const float*)d_in[0];
    const float* Wd   = (const float*)d_in[1];
    const float* Wm   = (const float*)d_in[2];
    float* out = (float*)d_out;

    cudaMemcpyToSymbolAsync(cWd, Wd, GC0 * 4 * sizeof(float), 0,
                            cudaMemcpyDeviceToDevice);

    size_t smF = (size_t)3 * NPTS * sizeof(float);                        // 48K
    size_t smC = (size_t)8 * 16 * FS * sizeof(uint32_t)
               + (size_t)8 * KNN * sizeof(int);                           // 34.8K

    cudaFuncSetAttribute(fps_kernel,  cudaFuncAttributeMaxDynamicSharedMemorySize, (int)smF);
    cudaFuncSetAttribute(conv_kernel, cudaFuncAttributeMaxDynamicSharedMemorySize, (int)smC);

    fps_kernel<<<GTOT + 4, FPS_THREADS, smF>>>(xyzs, Wm, out);   // fps + prep
    conv_kernel<<<dim3(16, GTOT), 256, smC>>>(xyzs, out);
}